// round 2
// baseline (speedup 1.0000x reference)
#include <cuda_runtime.h>
#include <cstdint>

#define F    128
#define OUTF 128
#define MTILE 64
#define KC    64

struct AdjPtrs { const int* p[10]; };

__device__ __forceinline__ unsigned long long pack2(float lo, float hi) {
    unsigned long long r;
    asm("mov.b64 %0, {%1, %2};" : "=l"(r) : "f"(lo), "f"(hi));
    return r;
}
__device__ __forceinline__ void ffma2(unsigned long long& d,
                                      unsigned long long a,
                                      unsigned long long b) {
    asm("fma.rn.f32x2 %0, %1, %2, %0;" : "+l"(d) : "l"(a), "l"(b));
}
__device__ __forceinline__ float2 unpack2(unsigned long long v) {
    float2 r;
    asm("mov.b64 {%0, %1}, %2;" : "=f"(r.x), "=f"(r.y) : "l"(v));
    return r;
}

__global__ __launch_bounds__(256, 2)
void graphconv_kernel(const float* __restrict__ af,
                      AdjPtrs adj,
                      const float* __restrict__ W0,   const float* __restrict__ b0,
                      const float* __restrict__ Wrel, const float* __restrict__ brel,
                      const float* __restrict__ Wself,const float* __restrict__ bself,
                      float* __restrict__ out)
{
    extern __shared__ float smem[];
    // As_t: transposed A, [256 k][64 m], column XOR-swizzled. 64 KB.
    float (*As_t)[MTILE] = (float (*)[MTILE])smem;
    // Bs: weight chunk [64 k][128 n]. 32 KB.
    float (*Bs)[OUTF] = (float (*)[OUTF])(smem + 256 * MTILE);

    const int cnt[11] = {25000,50000,100000,150000,100000,50000,5000,5000,5000,5000,5000};
    const int off[11] = {0,25000,75000,175000,325000,425000,475000,480000,485000,490000,495000};

    int seg = 0, btile = blockIdx.x;
    while (true) {
        int nt = (cnt[seg] + MTILE - 1) / MTILE;
        if (btile < nt) break;
        btile -= nt;
        ++seg;
    }
    const int deg  = seg;
    const int row0 = off[seg] + btile * MTILE;
    const int rows = min(MTILE, cnt[seg] - btile * MTILE);

    const int tid  = threadIdx.x;
    const int lane = tid & 31;
    const int wrp  = tid >> 5;

    // ---------------- gather / mean phase (transposed, swizzled stores) -------
    // warp w builds rows m = w*8 .. w*8+7. lane holds features 4*lane..4*lane+3.
    {
        const int* adjp = (deg > 0) ? adj.p[deg - 1] : (const int*)0;
        const int swz = (lane & 15) << 2;          // c(k) for k>>2 == lane (mod 16)
        const int kr  = 4 * lane;                  // rel feature base row in As_t
        #pragma unroll 1
        for (int i = 0; i < 8; ++i) {
            int m = wrp * 8 + i;
            if (m >= rows) continue;
            int colm = m ^ swz;
            size_t grow = (size_t)(row0 + m);
            float4 s = *(const float4*)(af + grow * F + lane * 4);
            if (deg == 0) {
                As_t[kr + 0][colm] = s.x;
                As_t[kr + 1][colm] = s.y;
                As_t[kr + 2][colm] = s.z;
                As_t[kr + 3][colm] = s.w;
            } else {
                const int* ar = adjp + (size_t)(btile * MTILE + m) * deg;
                float4 acc4 = make_float4(0.f, 0.f, 0.f, 0.f);
                for (int j = 0; j < deg; ++j) {
                    size_t idx = (size_t)ar[j];
                    float4 v = *(const float4*)(af + idx * F + lane * 4);
                    acc4.x += v.x; acc4.y += v.y; acc4.z += v.z; acc4.w += v.w;
                }
                float inv = 1.0f / (float)deg;
                // rel features: k = 4*lane + j
                As_t[kr + 0][colm] = acc4.x * inv;
                As_t[kr + 1][colm] = acc4.y * inv;
                As_t[kr + 2][colm] = acc4.z * inv;
                As_t[kr + 3][colm] = acc4.w * inv;
                // self features: k = 128 + 4*lane + j  (same swizzle: (k>>2)&15 == lane&15)
                As_t[128 + kr + 0][colm] = s.x;
                As_t[128 + kr + 1][colm] = s.y;
                As_t[128 + kr + 2][colm] = s.z;
                As_t[128 + kr + 3][colm] = s.w;
            }
        }
    }
    __syncthreads();

    // ---------------- GEMM phase ----------------
    const float* Bsrc0;
    const float* Bsrc1 = (const float*)0;
    if (deg == 0) {
        Bsrc0 = W0;
    } else {
        Bsrc0 = Wrel  + (size_t)(deg - 1) * F * OUTF;
        Bsrc1 = Wself + (size_t)(deg - 1) * F * OUTF;
    }

    const int tx4 = lane * 4;     // N cols tx4..tx4+3
    const int ty8 = wrp * 8;      // M rows ty8..ty8+7
    const int tyq  = ty8 >> 2;    // 2*wrp
    const int kdepth  = (deg == 0) ? 128 : 256;
    const int nchunks = kdepth / KC;

    // acc[p][n]: packed pair (m = ty8+2p, ty8+2p+1), col tx4+n
    unsigned long long acc[4][4];
    #pragma unroll
    for (int p = 0; p < 4; ++p)
        #pragma unroll
        for (int n = 0; n < 4; ++n) acc[p][n] = 0ULL;

    for (int c = 0; c < nchunks; ++c) {
        const float* src = (c < 2) ? (Bsrc0 + (size_t)c * KC * OUTF)
                                   : (Bsrc1 + (size_t)(c - 2) * KC * OUTF);
        // load 64x128 weight chunk: 2048 float4s across 256 threads
        #pragma unroll
        for (int r = 0; r < 8; ++r) {
            int e  = tid + r * 256;
            int kk = e >> 5;
            int nn = (e & 31) << 2;
            *(float4*)&Bs[kk][nn] = __ldg((const float4*)(src + (size_t)kk * OUTF + nn));
        }
        __syncthreads();

        const int kbase = c * KC;
        #pragma unroll 4
        for (int kq = 0; kq < KC / 4; ++kq) {
            // swizzle constant for this 4-k group: c4 = kq (kbase/4 is multiple of 16)
            const int g0 = ((tyq     ^ kq) << 2);
            const int g1 = (((tyq+1) ^ kq) << 2);
            const int kg = kbase + kq * 4;
            const int kl = kq * 4;
            #pragma unroll
            for (int j = 0; j < 4; ++j) {
                // A: two LDS.128 -> 4 ready m-pairs (broadcast, conflict-free)
                ulonglong2 a01 = *(const ulonglong2*)&As_t[kg + j][g0];
                ulonglong2 a23 = *(const ulonglong2*)&As_t[kg + j][g1];
                // B: one LDS.128 -> 4 scalars, packed (b,b)
                float4 b = *(const float4*)&Bs[kl + j][tx4];
                unsigned long long bp0 = pack2(b.x, b.x);
                unsigned long long bp1 = pack2(b.y, b.y);
                unsigned long long bp2 = pack2(b.z, b.z);
                unsigned long long bp3 = pack2(b.w, b.w);

                ffma2(acc[0][0], a01.x, bp0);
                ffma2(acc[0][1], a01.x, bp1);
                ffma2(acc[0][2], a01.x, bp2);
                ffma2(acc[0][3], a01.x, bp3);
                ffma2(acc[1][0], a01.y, bp0);
                ffma2(acc[1][1], a01.y, bp1);
                ffma2(acc[1][2], a01.y, bp2);
                ffma2(acc[1][3], a01.y, bp3);
                ffma2(acc[2][0], a23.x, bp0);
                ffma2(acc[2][1], a23.x, bp1);
                ffma2(acc[2][2], a23.x, bp2);
                ffma2(acc[2][3], a23.x, bp3);
                ffma2(acc[3][0], a23.y, bp0);
                ffma2(acc[3][1], a23.y, bp1);
                ffma2(acc[3][2], a23.y, bp2);
                ffma2(acc[3][3], a23.y, bp3);
            }
        }
        __syncthreads();
    }

    // ---------------- epilogue: bias + ReLU + store ----------------
    float4 bias;
    if (deg == 0) {
        bias = *(const float4*)(b0 + tx4);
    } else {
        float4 br = *(const float4*)(brel  + (size_t)(deg - 1) * OUTF + tx4);
        float4 bs = *(const float4*)(bself + (size_t)(deg - 1) * OUTF + tx4);
        bias.x = br.x + bs.x; bias.y = br.y + bs.y;
        bias.z = br.z + bs.z; bias.w = br.w + bs.w;
    }

    #pragma unroll
    for (int p = 0; p < 4; ++p) {
        float2 v0 = unpack2(acc[p][0]);
        float2 v1 = unpack2(acc[p][1]);
        float2 v2 = unpack2(acc[p][2]);
        float2 v3 = unpack2(acc[p][3]);
        int m0 = ty8 + 2 * p;
        int m1 = m0 + 1;
        if (m0 < rows) {
            float4 o;
            o.x = fmaxf(v0.x + bias.x, 0.f);
            o.y = fmaxf(v1.x + bias.y, 0.f);
            o.z = fmaxf(v2.x + bias.z, 0.f);
            o.w = fmaxf(v3.x + bias.w, 0.f);
            *(float4*)(out + (size_t)(row0 + m0) * OUTF + tx4) = o;
        }
        if (m1 < rows) {
            float4 o;
            o.x = fmaxf(v0.y + bias.x, 0.f);
            o.y = fmaxf(v1.y + bias.y, 0.f);
            o.z = fmaxf(v2.y + bias.z, 0.f);
            o.w = fmaxf(v3.y + bias.w, 0.f);
            *(float4*)(out + (size_t)(row0 + m1) * OUTF + tx4) = o;
        }
    }
}

extern "C" void kernel_launch(void* const* d_in, const int* in_sizes, int n_in,
                              void* d_out, int out_size)
{
    const float* af = (const float*)d_in[0];
    AdjPtrs adj;
    for (int i = 0; i < 10; ++i) adj.p[i] = (const int*)d_in[2 + i];
    const float* W0    = (const float*)d_in[12];
    const float* b0    = (const float*)d_in[13];
    const float* Wrel  = (const float*)d_in[14];
    const float* brel  = (const float*)d_in[15];
    const float* Wself = (const float*)d_in[16];
    const float* bself = (const float*)d_in[17];
    float* out = (float*)d_out;

    static const int cnt[11] = {25000,50000,100000,150000,100000,50000,5000,5000,5000,5000,5000};
    int tiles = 0;
    for (int i = 0; i < 11; ++i) tiles += (cnt[i] + MTILE - 1) / MTILE;  // 7820

    size_t shmem = (size_t)(256 * MTILE + KC * OUTF) * sizeof(float);   // 96 KB
    cudaFuncSetAttribute(graphconv_kernel,
                         cudaFuncAttributeMaxDynamicSharedMemorySize, (int)shmem);
    graphconv_kernel<<<tiles, 256, shmem>>>(af, adj, W0, b0, Wrel, brel, Wself, bself, out);
}

// round 4
// speedup vs baseline: 1.4718x; 1.4718x over previous
#include <cuda_runtime.h>
#include <cuda_bf16.h>
#include <cstdint>

#define MTILE 64

struct AdjPtrs { const int* p[10]; };

// Pre-split, pre-swizzled weights: [seg][kchunk(32k)][8KB] bf16, plus combined bias.
__device__ __align__(1024) unsigned char g_Wh[11][8][8192];
__device__ __align__(1024) unsigned char g_Wl[11][8][8192];
__device__ float g_bias[11][128];

__device__ __forceinline__ uint32_t smem_u32(const void* p) {
    uint32_t a;
    asm("{ .reg .u64 t; cvta.to.shared.u64 t, %1; cvt.u32.u64 %0, t; }" : "=r"(a) : "l"(p));
    return a;
}
__device__ __forceinline__ void ldsm4(uint32_t* r, uint32_t a) {
    asm volatile("ldmatrix.sync.aligned.m8n8.x4.shared.b16 {%0,%1,%2,%3}, [%4];"
        : "=r"(r[0]), "=r"(r[1]), "=r"(r[2]), "=r"(r[3]) : "r"(a));
}
__device__ __forceinline__ void ldsm4t(uint32_t* r, uint32_t a) {
    asm volatile("ldmatrix.sync.aligned.m8n8.x4.trans.shared.b16 {%0,%1,%2,%3}, [%4];"
        : "=r"(r[0]), "=r"(r[1]), "=r"(r[2]), "=r"(r[3]) : "r"(a));
}
__device__ __forceinline__ void mma16816(float* c, const uint32_t* a, uint32_t b0, uint32_t b1) {
    asm volatile("mma.sync.aligned.m16n8k16.row.col.f32.bf16.bf16.f32 "
        "{%0,%1,%2,%3}, {%4,%5,%6,%7}, {%8,%9}, {%0,%1,%2,%3};"
        : "+f"(c[0]), "+f"(c[1]), "+f"(c[2]), "+f"(c[3])
        : "r"(a[0]), "r"(a[1]), "r"(a[2]), "r"(a[3]), "r"(b0), "r"(b1));
}
__device__ __forceinline__ void cpasync16(uint32_t dst, const void* src) {
    asm volatile("cp.async.cg.shared.global [%0], [%1], 16;" :: "r"(dst), "l"(src) : "memory");
}
#define CP_COMMIT() asm volatile("cp.async.commit_group;" ::: "memory")
#define CP_WAIT1()  asm volatile("cp.async.wait_group 1;" ::: "memory")
#define CP_WAIT0()  asm volatile("cp.async.wait_group 0;" ::: "memory")

__device__ __forceinline__ unsigned long long pack4bf(float a0, float a1, float a2, float a3) {
    __nv_bfloat162 p0 = __floats2bfloat162_rn(a0, a1);
    __nv_bfloat162 p1 = __floats2bfloat162_rn(a2, a3);
    unsigned int u0 = *(unsigned int*)&p0;
    unsigned int u1 = *(unsigned int*)&p1;
    return (unsigned long long)u0 | ((unsigned long long)u1 << 32);
}

// ---------------- weight prep: fp32 -> pre-swizzled bf16 hi/lo chunks ----------------
__global__ void prep_weights(const float* __restrict__ W0,   const float* __restrict__ b0,
                             const float* __restrict__ Wrel, const float* __restrict__ brel,
                             const float* __restrict__ Wself,const float* __restrict__ bself)
{
    int idx = blockIdx.x * blockDim.x + threadIdx.x;
    if (idx >= 11 * 256 * 128) return;
    int n = idx & 127;
    int k = (idx >> 7) & 255;     // 0..127 rel slot, 128..255 self slot
    int s = idx >> 15;
    float w;
    if (s == 0) w = (k < 128) ? 0.f : W0[(size_t)(k - 128) * 128 + n];
    else        w = (k < 128) ? Wrel[((size_t)(s - 1) * 128 + k) * 128 + n]
                              : Wself[((size_t)(s - 1) * 128 + (k - 128)) * 128 + n];
    __nv_bfloat16 hi = __float2bfloat16(w);
    __nv_bfloat16 lo = __float2bfloat16(w - __bfloat162float(hi));
    int b = (((k & 31) * 256) + n * 2) ^ ((k & 7) << 4);
    *(__nv_bfloat16*)(g_Wh[s][k >> 5] + b) = hi;
    *(__nv_bfloat16*)(g_Wl[s][k >> 5] + b) = lo;
    if (k == 0) g_bias[s][n] = (s == 0) ? b0[n] : brel[(s - 1) * 128 + n] + bself[(s - 1) * 128 + n];
}

// ---------------- main fused kernel ----------------
__global__ __launch_bounds__(256, 2)
void graphconv_hmma(const float* __restrict__ af, AdjPtrs adj, float* __restrict__ out)
{
    extern __shared__ unsigned char dynsmem[];
    uint32_t base0 = smem_u32(dynsmem);
    uint32_t Abase = (base0 + 1023) & ~1023u;   // Ah: 64 x 256 bf16, swizzled (32KB)
    uint32_t ALbase = Abase + 32768;            // Al (32KB)
    uint32_t Bbase = Abase + 65536;             // 2 x 16KB (hi 8KB + lo 8KB per buf)
    unsigned char* Ap = dynsmem + (Abase - base0);

    const int cnt[11] = {25000,50000,100000,150000,100000,50000,5000,5000,5000,5000,5000};
    const int off[11] = {0,25000,75000,175000,325000,425000,475000,480000,485000,490000,495000};

    int seg = 0, btile = blockIdx.x;
    while (true) {
        int nt = (cnt[seg] + MTILE - 1) / MTILE;
        if (btile < nt) break;
        btile -= nt;
        ++seg;
    }
    const int deg  = seg;
    const int row0 = off[seg] + btile * MTILE;
    const int rows = min(MTILE, cnt[seg] - btile * MTILE);

    const int tid  = threadIdx.x;
    const int lane = tid & 31;
    const int wrp  = tid >> 5;

    const int c0  = (deg == 0) ? 4 : 0;   // deg0: only self half (k 128..255)
    const int nch = 8 - c0;

    // -------- prefetch first weight chunk (overlaps gather) --------
    {
        const unsigned char* sh = g_Wh[seg][c0];
        const unsigned char* sl = g_Wl[seg][c0];
        cpasync16(Bbase + tid * 16,               sh + tid * 16);
        cpasync16(Bbase + 4096 + tid * 16,        sh + 4096 + tid * 16);
        cpasync16(Bbase + 8192 + tid * 16,        sl + tid * 16);
        cpasync16(Bbase + 8192 + 4096 + tid * 16, sl + 4096 + tid * 16);
        CP_COMMIT();
    }

    // -------- gather / mean / bf16 hi-lo split into swizzled A --------
    {
        const int* adjp = (deg > 0) ? adj.p[deg - 1] : (const int*)0;
        const int k0 = lane * 4;
        #pragma unroll 1
        for (int i = 0; i < 8; ++i) {
            int m = wrp * 8 + i;
            if (m >= rows) continue;
            float4 s = *(const float4*)(af + (size_t)(row0 + m) * 128 + k0);
            int swz = (m & 7) << 4;
            int offS = ((m * 512 + 256 + 8 * lane) ^ swz);
            float sh0 = __bfloat162float(__float2bfloat16(s.x));
            float sh1 = __bfloat162float(__float2bfloat16(s.y));
            float sh2 = __bfloat162float(__float2bfloat16(s.z));
            float sh3 = __bfloat162float(__float2bfloat16(s.w));
            *(unsigned long long*)(Ap + offS)         = pack4bf(s.x, s.y, s.z, s.w);
            *(unsigned long long*)(Ap + 32768 + offS) = pack4bf(s.x - sh0, s.y - sh1, s.z - sh2, s.w - sh3);
            if (deg > 0) {
                const int* ar = adjp + (size_t)(btile * MTILE + m) * deg;
                float4 r4 = make_float4(0.f, 0.f, 0.f, 0.f);
                for (int j = 0; j < deg; ++j) {
                    float4 v = *(const float4*)(af + (size_t)ar[j] * 128 + k0);
                    r4.x += v.x; r4.y += v.y; r4.z += v.z; r4.w += v.w;
                }
                float inv = 1.0f / (float)deg;
                r4.x *= inv; r4.y *= inv; r4.z *= inv; r4.w *= inv;
                int offR = ((m * 512 + 8 * lane) ^ swz);
                float rh0 = __bfloat162float(__float2bfloat16(r4.x));
                float rh1 = __bfloat162float(__float2bfloat16(r4.y));
                float rh2 = __bfloat162float(__float2bfloat16(r4.z));
                float rh3 = __bfloat162float(__float2bfloat16(r4.w));
                *(unsigned long long*)(Ap + offR)         = pack4bf(r4.x, r4.y, r4.z, r4.w);
                *(unsigned long long*)(Ap + 32768 + offR) = pack4bf(r4.x - rh0, r4.y - rh1, r4.z - rh2, r4.w - rh3);
            }
        }
    }
    __syncthreads();

    // -------- warp tiling: 2 (M32) x 4 (N32) --------
    const int wm = wrp >> 2;         // 0..1
    const int wn = wrp & 3;          // 0..3

    // A ldmatrix per-thread bases
    const int arow0 = wm * 32 + (lane & 15);        // mt=0 row
    const int aswz  = (arow0 & 7) << 4;
    const int aLow  = (lane >> 4) << 4;             // k-half byte offset
    const uint32_t aB0 = Abase + arow0 * 512;
    const uint32_t aB1 = aB0 + 16 * 512;            // mt=1 (+16 rows): same swizzle

    // B ldmatrix per-thread offsets (within a 8KB chunk image)
    const int bswz = (lane & 7) << 4;
    const int bn   = wn * 32 + 8 * (lane >> 4);
    const uint32_t bOff0 = (lane & 15) * 256 + (uint32_t)(((bn +  0) * 2) ^ bswz);
    const uint32_t bOff1 = (lane & 15) * 256 + (uint32_t)(((bn + 16) * 2) ^ bswz);

    float acc[2][4][4];
    #pragma unroll
    for (int a = 0; a < 2; ++a)
        #pragma unroll
        for (int b = 0; b < 4; ++b)
            #pragma unroll
            for (int v = 0; v < 4; ++v) acc[a][b][v] = 0.f;

    #pragma unroll 1
    for (int ci = 0; ci < nch; ++ci) {
        const int c = c0 + ci;
        const uint32_t bufo = (uint32_t)(ci & 1) * 16384;
        if (ci + 1 < nch) {
            const unsigned char* sh = g_Wh[seg][c + 1];
            const unsigned char* sl = g_Wl[seg][c + 1];
            uint32_t d = Bbase + (((ci + 1) & 1) * 16384);
            cpasync16(d + tid * 16,               sh + tid * 16);
            cpasync16(d + 4096 + tid * 16,        sh + 4096 + tid * 16);
            cpasync16(d + 8192 + tid * 16,        sl + tid * 16);
            cpasync16(d + 8192 + 4096 + tid * 16, sl + 4096 + tid * 16);
            CP_COMMIT();
            CP_WAIT1();
        } else {
            CP_WAIT0();
        }
        __syncthreads();

        #pragma unroll
        for (int klh = 0; klh < 2; ++klh) {
            const int kl = klh * 16;
            const int kg = c * 32 + kl;
            uint32_t ah0[4], ah1[4], al0[4], al1[4];
            const uint32_t ak = (uint32_t)((aLow + kg * 2) ^ aswz);
            ldsm4(ah0, aB0 + ak);
            ldsm4(ah1, aB1 + ak);
            ldsm4(al0, aB0 + 32768 + ak);
            ldsm4(al1, aB1 + 32768 + ak);
            #pragma unroll
            for (int p = 0; p < 2; ++p) {
                uint32_t bh[4], bl[4];
                uint32_t ba = Bbase + bufo + (uint32_t)(kl * 256) + (p ? bOff1 : bOff0);
                ldsm4t(bh, ba);
                ldsm4t(bl, ba + 8192);
                const int n0 = 2 * p, n1 = 2 * p + 1;
                mma16816(acc[0][n0], ah0, bh[0], bh[1]);
                mma16816(acc[0][n1], ah0, bh[2], bh[3]);
                mma16816(acc[1][n0], ah1, bh[0], bh[1]);
                mma16816(acc[1][n1], ah1, bh[2], bh[3]);
                mma16816(acc[0][n0], al0, bh[0], bh[1]);
                mma16816(acc[0][n1], al0, bh[2], bh[3]);
                mma16816(acc[1][n0], al1, bh[0], bh[1]);
                mma16816(acc[1][n1], al1, bh[2], bh[3]);
                mma16816(acc[0][n0], ah0, bl[0], bl[1]);
                mma16816(acc[0][n1], ah0, bl[2], bl[3]);
                mma16816(acc[1][n0], ah1, bl[0], bl[1]);
                mma16816(acc[1][n1], ah1, bl[2], bl[3]);
            }
        }
        __syncthreads();
    }

    // -------- epilogue: bias + ReLU + store --------
    const int colb = wn * 32 + 2 * (lane & 3);
    #pragma unroll
    for (int mt = 0; mt < 2; ++mt) {
        const int rbase = wm * 32 + mt * 16 + (lane >> 2);
        #pragma unroll
        for (int h = 0; h < 2; ++h) {
            const int m = rbase + h * 8;
            if (m < rows) {
                float* orow = out + (size_t)(row0 + m) * 128;
                #pragma unroll
                for (int nt = 0; nt < 4; ++nt) {
                    const int col = colb + nt * 8;
                    float2 b2 = *(const float2*)&g_bias[seg][col];
                    float2 o;
                    o.x = fmaxf(acc[mt][nt][h * 2 + 0] + b2.x, 0.f);
                    o.y = fmaxf(acc[mt][nt][h * 2 + 1] + b2.y, 0.f);
                    *(float2*)(orow + col) = o;
                }
            }
        }
    }
}

extern "C" void kernel_launch(void* const* d_in, const int* in_sizes, int n_in,
                              void* d_out, int out_size)
{
    const float* af = (const float*)d_in[0];
    AdjPtrs adj;
    for (int i = 0; i < 10; ++i) adj.p[i] = (const int*)d_in[2 + i];
    const float* W0    = (const float*)d_in[12];
    const float* b0    = (const float*)d_in[13];
    const float* Wrel  = (const float*)d_in[14];
    const float* brel  = (const float*)d_in[15];
    const float* Wself = (const float*)d_in[16];
    const float* bself = (const float*)d_in[17];
    float* out = (float*)d_out;

    prep_weights<<<(11 * 256 * 128 + 255) / 256, 256>>>(W0, b0, Wrel, brel, Wself, bself);

    static const int cnt[11] = {25000,50000,100000,150000,100000,50000,5000,5000,5000,5000,5000};
    int tiles = 0;
    for (int i = 0; i < 11; ++i) tiles += (cnt[i] + MTILE - 1) / MTILE;  // 7820

    size_t shmem = 65536 + 32768 + 1024;   // A(64K) + B(32K) + align slack
    cudaFuncSetAttribute(graphconv_hmma,
                         cudaFuncAttributeMaxDynamicSharedMemorySize, (int)shmem);
    graphconv_hmma<<<tiles, 256, shmem>>>(af, adj, out);
}

// round 5
// speedup vs baseline: 1.9752x; 1.3420x over previous
#include <cuda_runtime.h>
#include <cuda_bf16.h>
#include <cstdint>

#define MTILE 64

struct AdjPtrs { const int* p[10]; };

// Pre-split, pre-swizzled weights: [seg][kchunk(32k)][8KB] bf16, plus combined bias.
__device__ __align__(1024) unsigned char g_Wh[11][8][8192];
__device__ __align__(1024) unsigned char g_Wl[11][8][8192];
__device__ float g_bias[11][128];

__device__ __forceinline__ uint32_t smem_u32(const void* p) {
    uint32_t a;
    asm("{ .reg .u64 t; cvta.to.shared.u64 t, %1; cvt.u32.u64 %0, t; }" : "=r"(a) : "l"(p));
    return a;
}
__device__ __forceinline__ void ldsm4(uint32_t* r, uint32_t a) {
    asm volatile("ldmatrix.sync.aligned.m8n8.x4.shared.b16 {%0,%1,%2,%3}, [%4];"
        : "=r"(r[0]), "=r"(r[1]), "=r"(r[2]), "=r"(r[3]) : "r"(a));
}
__device__ __forceinline__ void ldsm4t(uint32_t* r, uint32_t a) {
    asm volatile("ldmatrix.sync.aligned.m8n8.x4.trans.shared.b16 {%0,%1,%2,%3}, [%4];"
        : "=r"(r[0]), "=r"(r[1]), "=r"(r[2]), "=r"(r[3]) : "r"(a));
}
__device__ __forceinline__ void mma16816(float* c, const uint32_t* a, uint32_t b0, uint32_t b1) {
    asm volatile("mma.sync.aligned.m16n8k16.row.col.f32.bf16.bf16.f32 "
        "{%0,%1,%2,%3}, {%4,%5,%6,%7}, {%8,%9}, {%0,%1,%2,%3};"
        : "+f"(c[0]), "+f"(c[1]), "+f"(c[2]), "+f"(c[3])
        : "r"(a[0]), "r"(a[1]), "r"(a[2]), "r"(a[3]), "r"(b0), "r"(b1));
}
__device__ __forceinline__ void cpasync16(uint32_t dst, const void* src) {
    asm volatile("cp.async.cg.shared.global [%0], [%1], 16;" :: "r"(dst), "l"(src) : "memory");
}
#define CP_COMMIT() asm volatile("cp.async.commit_group;" ::: "memory")
#define CP_WAIT1()  asm volatile("cp.async.wait_group 1;" ::: "memory")
#define CP_WAIT0()  asm volatile("cp.async.wait_group 0;" ::: "memory")

__device__ __forceinline__ unsigned long long pack4bf(float a0, float a1, float a2, float a3) {
    __nv_bfloat162 p0 = __floats2bfloat162_rn(a0, a1);
    __nv_bfloat162 p1 = __floats2bfloat162_rn(a2, a3);
    unsigned int u0 = *(unsigned int*)&p0;
    unsigned int u1 = *(unsigned int*)&p1;
    return (unsigned long long)u0 | ((unsigned long long)u1 << 32);
}

// ---------------- weight prep: fp32 -> pre-swizzled bf16 hi/lo chunks ----------------
__global__ void prep_weights(const float* __restrict__ W0,   const float* __restrict__ b0,
                             const float* __restrict__ Wrel, const float* __restrict__ brel,
                             const float* __restrict__ Wself,const float* __restrict__ bself)
{
    int idx = blockIdx.x * blockDim.x + threadIdx.x;
    if (idx >= 11 * 256 * 128) return;
    int n = idx & 127;
    int k = (idx >> 7) & 255;     // 0..127 rel slot, 128..255 self slot
    int s = idx >> 15;
    float w;
    if (s == 0) w = (k < 128) ? 0.f : W0[(size_t)(k - 128) * 128 + n];
    else        w = (k < 128) ? Wrel[((size_t)(s - 1) * 128 + k) * 128 + n]
                              : Wself[((size_t)(s - 1) * 128 + (k - 128)) * 128 + n];
    __nv_bfloat16 hi = __float2bfloat16(w);
    __nv_bfloat16 lo = __float2bfloat16(w - __bfloat162float(hi));
    int b = (((k & 31) * 256) + n * 2) ^ ((k & 7) << 4);
    *(__nv_bfloat16*)(g_Wh[s][k >> 5] + b) = hi;
    *(__nv_bfloat16*)(g_Wl[s][k >> 5] + b) = lo;
    if (k == 0) g_bias[s][n] = (s == 0) ? b0[n] : brel[(s - 1) * 128 + n] + bself[(s - 1) * 128 + n];
}

// ---------------- degree-specialized gather: fully unrolled neighbor loads ----------
template<int DEG>
__device__ __forceinline__ void gather_deg(const float* __restrict__ af,
                                           const int* __restrict__ adjp,
                                           unsigned char* Ap,
                                           int row0, int abase_rows, int rows,
                                           int wrp, int lane)
{
    const int k0 = lane * 4;
    constexpr int UN = (DEG <= 2) ? 4 : (DEG <= 5 ? 2 : 1);
    #pragma unroll 1
    for (int ii = 0; ii < 8; ii += UN) {
        // ---- front-batch all loads of this group (UN rows) ----
        float4 selfv[UN];
        float4 nb[UN][DEG > 0 ? DEG : 1];
        #pragma unroll
        for (int u = 0; u < UN; ++u) {
            int m = wrp * 8 + ii + u;
            bool live = (m < rows);
            const float* srow = af + (size_t)(row0 + (live ? m : 0)) * 128 + k0;
            selfv[u] = *(const float4*)srow;
            if (DEG > 0) {
                int idxs[DEG > 0 ? DEG : 1];
                const int* ar = adjp + (size_t)(abase_rows + (live ? m : 0)) * DEG;
                #pragma unroll
                for (int j = 0; j < DEG; ++j) idxs[j] = __ldg(ar + j);
                #pragma unroll
                for (int j = 0; j < DEG; ++j)
                    nb[u][j] = *(const float4*)(af + (size_t)idxs[j] * 128 + k0);
            }
        }
        // ---- reduce / convert / store ----
        #pragma unroll
        for (int u = 0; u < UN; ++u) {
            int m = wrp * 8 + ii + u;
            if (m >= rows) continue;
            int swz  = (m & 7) << 4;
            int offS = ((m * 512 + 256 + 8 * lane) ^ swz);
            float4 s = selfv[u];
            float sh0 = __bfloat162float(__float2bfloat16(s.x));
            float sh1 = __bfloat162float(__float2bfloat16(s.y));
            float sh2 = __bfloat162float(__float2bfloat16(s.z));
            float sh3 = __bfloat162float(__float2bfloat16(s.w));
            *(unsigned long long*)(Ap + offS)         = pack4bf(s.x, s.y, s.z, s.w);
            *(unsigned long long*)(Ap + 32768 + offS) = pack4bf(s.x - sh0, s.y - sh1, s.z - sh2, s.w - sh3);
            if (DEG > 0) {
                float4 r4 = make_float4(0.f, 0.f, 0.f, 0.f);
                #pragma unroll
                for (int j = 0; j < DEG; ++j) {
                    r4.x += nb[u][j].x; r4.y += nb[u][j].y;
                    r4.z += nb[u][j].z; r4.w += nb[u][j].w;
                }
                constexpr float inv = 1.0f / (DEG > 0 ? (float)DEG : 1.0f);
                r4.x *= inv; r4.y *= inv; r4.z *= inv; r4.w *= inv;
                int offR = ((m * 512 + 8 * lane) ^ swz);
                float rh0 = __bfloat162float(__float2bfloat16(r4.x));
                float rh1 = __bfloat162float(__float2bfloat16(r4.y));
                float rh2 = __bfloat162float(__float2bfloat16(r4.z));
                float rh3 = __bfloat162float(__float2bfloat16(r4.w));
                *(unsigned long long*)(Ap + offR)         = pack4bf(r4.x, r4.y, r4.z, r4.w);
                *(unsigned long long*)(Ap + 32768 + offR) = pack4bf(r4.x - rh0, r4.y - rh1, r4.z - rh2, r4.w - rh3);
            }
        }
    }
}

// ---------------- main fused kernel ----------------
__global__ __launch_bounds__(256, 2)
void graphconv_hmma(const float* __restrict__ af, AdjPtrs adj, float* __restrict__ out)
{
    extern __shared__ unsigned char dynsmem[];
    uint32_t base0 = smem_u32(dynsmem);
    uint32_t Abase = (base0 + 1023) & ~1023u;   // Ah: 64 x 256 bf16, swizzled (32KB)
    uint32_t Bbase = Abase + 65536;             // 2 x 16KB (hi 8KB + lo 8KB per buf)
    unsigned char* Ap = dynsmem + (Abase - base0);

    const int cnt[11] = {25000,50000,100000,150000,100000,50000,5000,5000,5000,5000,5000};
    const int off[11] = {0,25000,75000,175000,325000,425000,475000,480000,485000,490000,495000};

    int seg = 0, btile = blockIdx.x;
    while (true) {
        int nt = (cnt[seg] + MTILE - 1) / MTILE;
        if (btile < nt) break;
        btile -= nt;
        ++seg;
    }
    const int deg  = seg;
    const int row0 = off[seg] + btile * MTILE;
    const int rows = min(MTILE, cnt[seg] - btile * MTILE);

    const int tid  = threadIdx.x;
    const int lane = tid & 31;
    const int wrp  = tid >> 5;

    const int c0  = (deg == 0) ? 4 : 0;   // deg0: only self half (k 128..255)
    const int nch = 8 - c0;

    // -------- prefetch first weight chunk (overlaps gather) --------
    {
        const unsigned char* sh = g_Wh[seg][c0];
        const unsigned char* sl = g_Wl[seg][c0];
        cpasync16(Bbase + tid * 16,               sh + tid * 16);
        cpasync16(Bbase + 4096 + tid * 16,        sh + 4096 + tid * 16);
        cpasync16(Bbase + 8192 + tid * 16,        sl + tid * 16);
        cpasync16(Bbase + 8192 + 4096 + tid * 16, sl + 4096 + tid * 16);
        CP_COMMIT();
    }

    // -------- gather / mean / bf16 hi-lo split into swizzled A (deg-specialized) ----
    {
        const int* adjp = (deg > 0) ? adj.p[deg - 1] : (const int*)0;
        const int ab = btile * MTILE;
        switch (deg) {
            case 0:  gather_deg<0 >(af, adjp, Ap, row0, ab, rows, wrp, lane); break;
            case 1:  gather_deg<1 >(af, adjp, Ap, row0, ab, rows, wrp, lane); break;
            case 2:  gather_deg<2 >(af, adjp, Ap, row0, ab, rows, wrp, lane); break;
            case 3:  gather_deg<3 >(af, adjp, Ap, row0, ab, rows, wrp, lane); break;
            case 4:  gather_deg<4 >(af, adjp, Ap, row0, ab, rows, wrp, lane); break;
            case 5:  gather_deg<5 >(af, adjp, Ap, row0, ab, rows, wrp, lane); break;
            case 6:  gather_deg<6 >(af, adjp, Ap, row0, ab, rows, wrp, lane); break;
            case 7:  gather_deg<7 >(af, adjp, Ap, row0, ab, rows, wrp, lane); break;
            case 8:  gather_deg<8 >(af, adjp, Ap, row0, ab, rows, wrp, lane); break;
            case 9:  gather_deg<9 >(af, adjp, Ap, row0, ab, rows, wrp, lane); break;
            default: gather_deg<10>(af, adjp, Ap, row0, ab, rows, wrp, lane); break;
        }
    }
    __syncthreads();

    // -------- warp tiling: 2 (M32) x 4 (N32) --------
    const int wm = wrp >> 2;         // 0..1
    const int wn = wrp & 3;          // 0..3

    const int arow0 = wm * 32 + (lane & 15);
    const int aswz  = (arow0 & 7) << 4;
    const int aLow  = (lane >> 4) << 4;
    const uint32_t aB0 = Abase + arow0 * 512;
    const uint32_t aB1 = aB0 + 16 * 512;

    const int bswz = (lane & 7) << 4;
    const int bn   = wn * 32 + 8 * (lane >> 4);
    const uint32_t bOff0 = (lane & 15) * 256 + (uint32_t)(((bn +  0) * 2) ^ bswz);
    const uint32_t bOff1 = (lane & 15) * 256 + (uint32_t)(((bn + 16) * 2) ^ bswz);

    float acc[2][4][4];
    #pragma unroll
    for (int a = 0; a < 2; ++a)
        #pragma unroll
        for (int b = 0; b < 4; ++b)
            #pragma unroll
            for (int v = 0; v < 4; ++v) acc[a][b][v] = 0.f;

    #pragma unroll 1
    for (int ci = 0; ci < nch; ++ci) {
        const int c = c0 + ci;
        const uint32_t bufo = (uint32_t)(ci & 1) * 16384;
        if (ci + 1 < nch) {
            const unsigned char* sh = g_Wh[seg][c + 1];
            const unsigned char* sl = g_Wl[seg][c + 1];
            uint32_t d = Bbase + (((ci + 1) & 1) * 16384);
            cpasync16(d + tid * 16,               sh + tid * 16);
            cpasync16(d + 4096 + tid * 16,        sh + 4096 + tid * 16);
            cpasync16(d + 8192 + tid * 16,        sl + tid * 16);
            cpasync16(d + 8192 + 4096 + tid * 16, sl + 4096 + tid * 16);
            CP_COMMIT();
            CP_WAIT1();
        } else {
            CP_WAIT0();
        }
        __syncthreads();

        #pragma unroll
        for (int klh = 0; klh < 2; ++klh) {
            const int kl = klh * 16;
            const int kg = c * 32 + kl;
            uint32_t ah0[4], ah1[4], al0[4], al1[4];
            const uint32_t ak = (uint32_t)((aLow + kg * 2) ^ aswz);
            ldsm4(ah0, aB0 + ak);
            ldsm4(ah1, aB1 + ak);
            ldsm4(al0, aB0 + 32768 + ak);
            ldsm4(al1, aB1 + 32768 + ak);
            #pragma unroll
            for (int p = 0; p < 2; ++p) {
                uint32_t bh[4], bl[4];
                uint32_t ba = Bbase + bufo + (uint32_t)(kl * 256) + (p ? bOff1 : bOff0);
                ldsm4t(bh, ba);
                ldsm4t(bl, ba + 8192);
                const int n0 = 2 * p, n1 = 2 * p + 1;
                mma16816(acc[0][n0], ah0, bh[0], bh[1]);
                mma16816(acc[0][n1], ah0, bh[2], bh[3]);
                mma16816(acc[1][n0], ah1, bh[0], bh[1]);
                mma16816(acc[1][n1], ah1, bh[2], bh[3]);
                mma16816(acc[0][n0], al0, bh[0], bh[1]);
                mma16816(acc[0][n1], al0, bh[2], bh[3]);
                mma16816(acc[1][n0], al1, bh[0], bh[1]);
                mma16816(acc[1][n1], al1, bh[2], bh[3]);
                mma16816(acc[0][n0], ah0, bl[0], bl[1]);
                mma16816(acc[0][n1], ah0, bl[2], bl[3]);
                mma16816(acc[1][n0], ah1, bl[0], bl[1]);
                mma16816(acc[1][n1], ah1, bl[2], bl[3]);
            }
        }
        __syncthreads();
    }

    // -------- epilogue: bias + ReLU + store --------
    const int colb = wn * 32 + 2 * (lane & 3);
    #pragma unroll
    for (int mt = 0; mt < 2; ++mt) {
        const int rbase = wm * 32 + mt * 16 + (lane >> 2);
        #pragma unroll
        for (int h = 0; h < 2; ++h) {
            const int m = rbase + h * 8;
            if (m < rows) {
                float* orow = out + (size_t)(row0 + m) * 128;
                #pragma unroll
                for (int nt = 0; nt < 4; ++nt) {
                    const int col = colb + nt * 8;
                    float2 b2 = *(const float2*)&g_bias[seg][col];
                    float2 o;
                    o.x = fmaxf(acc[mt][nt][h * 2 + 0] + b2.x, 0.f);
                    o.y = fmaxf(acc[mt][nt][h * 2 + 1] + b2.y, 0.f);
                    *(float2*)(orow + col) = o;
                }
            }
        }
    }
}

extern "C" void kernel_launch(void* const* d_in, const int* in_sizes, int n_in,
                              void* d_out, int out_size)
{
    const float* af = (const float*)d_in[0];
    AdjPtrs adj;
    for (int i = 0; i < 10; ++i) adj.p[i] = (const int*)d_in[2 + i];
    const float* W0    = (const float*)d_in[12];
    const float* b0    = (const float*)d_in[13];
    const float* Wrel  = (const float*)d_in[14];
    const float* brel  = (const float*)d_in[15];
    const float* Wself = (const float*)d_in[16];
    const float* bself = (const float*)d_in[17];
    float* out = (float*)d_out;

    prep_weights<<<(11 * 256 * 128 + 255) / 256, 256>>>(W0, b0, Wrel, brel, Wself, bself);

    static const int cnt[11] = {25000,50000,100000,150000,100000,50000,5000,5000,5000,5000,5000};
    int tiles = 0;
    for (int i = 0; i < 11; ++i) tiles += (cnt[i] + MTILE - 1) / MTILE;  // 7820

    size_t shmem = 65536 + 32768 + 1024;   // A(64K) + B(32K) + align slack
    cudaFuncSetAttribute(graphconv_hmma,
                         cudaFuncAttributeMaxDynamicSharedMemorySize, (int)shmem);
    graphconv_hmma<<<tiles, 256, shmem>>>(af, adj, out);
}